// round 4
// baseline (speedup 1.0000x reference)
#include <cuda_runtime.h>
#include <cuda_bf16.h>
#include <math.h>

#define MAX_N 50000
#define MAX_E 800000
#define HIST_BLOCKS 128

// Scratch (device globals — zero-initialized at load)
__device__ float g_h[MAX_N * 64];
__device__ float g_sd[MAX_N];
__device__ float g_ss[MAX_N];
__device__ int   g_deg[MAX_N];          // re-zeroed by scan_kernel each call
__device__ int   g_offs[MAX_N + 1];
__device__ int   g_cursor[MAX_N];
__device__ int2  g_edge[MAX_E];         // {src, score bits}

// ---------------------------------------------------------------------------
// f32x2 packed-math helpers (sm_103a)
// ---------------------------------------------------------------------------
__device__ __forceinline__ unsigned long long pack2(float x, float y) {
    unsigned long long r;
    asm("mov.b64 %0, {%1, %2};" : "=l"(r) : "f"(x), "f"(y));
    return r;
}
__device__ __forceinline__ float2 unpack2(unsigned long long v) {
    float2 f;
    asm("mov.b64 {%0, %1}, %2;" : "=f"(f.x), "=f"(f.y) : "l"(v));
    return f;
}
__device__ __forceinline__ void fma2(unsigned long long& d,
                                     unsigned long long a,
                                     unsigned long long b) {
    asm("fma.rn.f32x2 %0, %1, %2, %0;" : "+l"(d) : "l"(a), "l"(b));
}
__device__ __forceinline__ void mul2(unsigned long long& d,
                                     unsigned long long b) {
    asm("mul.rn.f32x2 %0, %0, %1;" : "+l"(d) : "l"(b));
}

// ---------------------------------------------------------------------------
// Fused: hist blocks do degree histogram; MLP blocks compute
// h = relu(relu(x@W1^T)@W2^T) for 128 rows + dots sd/ss.
// Phase A x/W1 tile loads are register-staged (prefetch next tile before
// computing current) to hide DRAM latency.
// ---------------------------------------------------------------------------
#define AS_OFF 0
#define BS_OFF 4224
#define W2_OFF 0
#define ZS_OFF 6272
#define SMEM_FLOATS (ZS_OFF + 64 * 132)   // 14720 floats = 58880 B

__global__ __launch_bounds__(256, 2)
void fused_mlp_hist_kernel(const float* __restrict__ x,
                           const float* __restrict__ W1,
                           const float* __restrict__ W2,
                           const float* __restrict__ a,
                           const int* __restrict__ dst,
                           int N, int E)
{
    const int tid = threadIdx.x;

    if (blockIdx.x < HIST_BLOCKS) {
        int stride = HIST_BLOCKS * 256;
        for (int i = blockIdx.x * 256 + tid; i < E; i += stride)
            atomicAdd(&g_deg[dst[i]], 1);
        return;
    }

    extern __shared__ float smem[];
    float* As  = smem + AS_OFF;
    float* Bs  = smem + BS_OFF;
    float* W2s = smem + W2_OFF;
    float* zs  = smem + ZS_OFF;

    const int tx   = tid & 15;
    const int ty   = tid >> 4;
    const int row0 = (blockIdx.x - HIST_BLOCKS) * 128;

    float a_d[4], a_s[4];
#pragma unroll
    for (int j = 0; j < 4; j++) {
        a_d[j] = a[tx * 4 + j];
        a_s[j] = a[64 + tx * 4 + j];
    }

    // per-thread staging indices
    const int xr0 = (tid + 0 * 256) >> 3, xk0 = (tid + 0 * 256) & 7;
    const int xr1 = (tid + 1 * 256) >> 3, xk1 = (tid + 1 * 256) & 7;
    const int xr2 = (tid + 2 * 256) >> 3, xk2 = (tid + 2 * 256) & 7;
    const int xr3 = (tid + 3 * 256) >> 3, xk3 = (tid + 3 * 256) & 7;
    const int wc0 = (tid + 0 * 256) >> 3, wk0 = (tid + 0 * 256) & 7;
    const int wc1 = (tid + 1 * 256) >> 3, wk1 = (tid + 1 * 256) & 7;
    int xrr[4] = {xr0, xr1, xr2, xr3};
    int xkk[4] = {xk0, xk1, xk2, xk3};
    int wcc[2] = {wc0, wc1};
    int wkk[2] = {wk0, wk1};

    float4 xa[4], wb[2];
    const float4 zero4 = make_float4(0.f, 0.f, 0.f, 0.f);
    // preload tile kb=0
#pragma unroll
    for (int q = 0; q < 4; q++) {
        int grow = row0 + xrr[q];
        xa[q] = (grow < N) ? *(const float4*)(x + (size_t)grow * 256 + xkk[q] * 4)
                           : zero4;
    }
#pragma unroll
    for (int q = 0; q < 2; q++)
        wb[q] = *(const float4*)(W1 + (size_t)wcc[q] * 256 + wkk[q] * 4);

    unsigned long long acc[4][4];
#pragma unroll
    for (int p = 0; p < 4; p++)
#pragma unroll
        for (int j = 0; j < 4; j++) acc[p][j] = 0ULL;

    for (int kb = 0; kb < 256; kb += 32) {
        // commit staged tile to smem (k-major, transposed)
#pragma unroll
        for (int q = 0; q < 4; q++) {
            As[(xkk[q] * 4 + 0) * 132 + xrr[q]] = xa[q].x;
            As[(xkk[q] * 4 + 1) * 132 + xrr[q]] = xa[q].y;
            As[(xkk[q] * 4 + 2) * 132 + xrr[q]] = xa[q].z;
            As[(xkk[q] * 4 + 3) * 132 + xrr[q]] = xa[q].w;
        }
#pragma unroll
        for (int q = 0; q < 2; q++) {
            Bs[(wkk[q] * 4 + 0) * 64 + wcc[q]] = wb[q].x;
            Bs[(wkk[q] * 4 + 1) * 64 + wcc[q]] = wb[q].y;
            Bs[(wkk[q] * 4 + 2) * 64 + wcc[q]] = wb[q].z;
            Bs[(wkk[q] * 4 + 3) * 64 + wcc[q]] = wb[q].w;
        }
        __syncthreads();

        // prefetch next tile while computing this one
        int kn = kb + 32;
        if (kn < 256) {
#pragma unroll
            for (int q = 0; q < 4; q++) {
                int grow = row0 + xrr[q];
                xa[q] = (grow < N)
                    ? *(const float4*)(x + (size_t)grow * 256 + kn + xkk[q] * 4)
                    : zero4;
            }
#pragma unroll
            for (int q = 0; q < 2; q++)
                wb[q] = *(const float4*)(W1 + (size_t)wcc[q] * 256 + kn + wkk[q] * 4);
        }

#pragma unroll 8
        for (int k = 0; k < 32; k++) {
            ulonglong2 av0 = *(const ulonglong2*)(As + k * 132 + ty * 8);
            ulonglong2 av1 = *(const ulonglong2*)(As + k * 132 + ty * 8 + 4);
            float4 bv = *(const float4*)(Bs + k * 64 + tx * 4);
            unsigned long long ap[4] = {av0.x, av0.y, av1.x, av1.y};
            unsigned long long bp[4] = {pack2(bv.x, bv.x), pack2(bv.y, bv.y),
                                        pack2(bv.z, bv.z), pack2(bv.w, bv.w)};
#pragma unroll
            for (int p = 0; p < 4; p++)
#pragma unroll
                for (int j = 0; j < 4; j++)
                    fma2(acc[p][j], ap[p], bp[j]);
        }
        __syncthreads();
    }

    // relu z -> zs (k-major), load W2 into freed region
#pragma unroll
    for (int p = 0; p < 4; p++)
#pragma unroll
        for (int j = 0; j < 4; j++) {
            float2 f = unpack2(acc[p][j]);
            f.x = f.x > 0.f ? f.x : 0.f;
            f.y = f.y > 0.f ? f.y : 0.f;
            int rl = ty * 8 + p * 2;
            int c  = tx * 4 + j;
            zs[c * 132 + rl]     = f.x;
            zs[c * 132 + rl + 1] = f.y;
        }
#pragma unroll
    for (int q = 0; q < 16; q++) {
        int idx = tid + q * 256;
        int c = idx >> 6;
        int k = idx & 63;
        W2s[k * 68 + c] = W2[idx];
    }
    __syncthreads();

    // ------------------ Phase B: h = relu(z @ W2^T), K=64 -------------------
    unsigned long long hacc[4][4];
#pragma unroll
    for (int p = 0; p < 4; p++)
#pragma unroll
        for (int j = 0; j < 4; j++) hacc[p][j] = 0ULL;

#pragma unroll 8
    for (int k = 0; k < 64; k++) {
        ulonglong2 av0 = *(const ulonglong2*)(zs + k * 132 + ty * 8);
        ulonglong2 av1 = *(const ulonglong2*)(zs + k * 132 + ty * 8 + 4);
        float4 bv = *(const float4*)(W2s + k * 68 + tx * 4);
        unsigned long long ap[4] = {av0.x, av0.y, av1.x, av1.y};
        unsigned long long bp[4] = {pack2(bv.x, bv.x), pack2(bv.y, bv.y),
                                    pack2(bv.z, bv.z), pack2(bv.w, bv.w)};
#pragma unroll
        for (int p = 0; p < 4; p++)
#pragma unroll
            for (int j = 0; j < 4; j++)
                fma2(hacc[p][j], ap[p], bp[j]);
    }

    // ------------------ Epilogue: relu, store h, dots -----------------------
    float hv[4][4][2];
    float pd[8], ps[8];
#pragma unroll
    for (int r = 0; r < 8; r++) { pd[r] = 0.f; ps[r] = 0.f; }

#pragma unroll
    for (int p = 0; p < 4; p++)
#pragma unroll
        for (int j = 0; j < 4; j++) {
            float2 f = unpack2(hacc[p][j]);
            f.x = f.x > 0.f ? f.x : 0.f;
            f.y = f.y > 0.f ? f.y : 0.f;
            hv[p][j][0] = f.x;
            hv[p][j][1] = f.y;
            pd[p * 2 + 0] = fmaf(f.x, a_d[j], pd[p * 2 + 0]);
            pd[p * 2 + 1] = fmaf(f.y, a_d[j], pd[p * 2 + 1]);
            ps[p * 2 + 0] = fmaf(f.x, a_s[j], ps[p * 2 + 0]);
            ps[p * 2 + 1] = fmaf(f.y, a_s[j], ps[p * 2 + 1]);
        }

#pragma unroll
    for (int p = 0; p < 4; p++)
#pragma unroll
        for (int q = 0; q < 2; q++) {
            int row = row0 + ty * 8 + p * 2 + q;
            if (row < N) {
                float4 o = make_float4(hv[p][0][q], hv[p][1][q],
                                       hv[p][2][q], hv[p][3][q]);
                *(float4*)(g_h + (size_t)row * 64 + tx * 4) = o;
            }
        }

#pragma unroll
    for (int off = 8; off; off >>= 1)
#pragma unroll
        for (int r = 0; r < 8; r++) {
            pd[r] += __shfl_xor_sync(0xFFFFFFFFu, pd[r], off);
            ps[r] += __shfl_xor_sync(0xFFFFFFFFu, ps[r], off);
        }
    if (tx == 0) {
#pragma unroll
        for (int r = 0; r < 8; r++) {
            int row = row0 + ty * 8 + r;
            if (row < N) { g_sd[row] = pd[r]; g_ss[row] = ps[r]; }
        }
    }
}

// ---------------------------------------------------------------------------
// Scan: exclusive prefix of g_deg -> g_offs/g_cursor; re-zero g_deg.
// ---------------------------------------------------------------------------
__global__ void scan_kernel(int N) {
    __shared__ int wsum[32];
    __shared__ int carry_s;
    int tid = threadIdx.x, lane = tid & 31, wid = tid >> 5;
    if (tid == 0) carry_s = 0;
    __syncthreads();
    for (int base = 0; base < N; base += 4096) {
        int i = base + tid * 4;
        int v0 = 0, v1 = 0, v2 = 0, v3 = 0;
        if (i + 3 < N) {
            int4 t = *(const int4*)&g_deg[i];
            v0 = t.x; v1 = t.y; v2 = t.z; v3 = t.w;
            *(int4*)&g_deg[i] = make_int4(0, 0, 0, 0);
        } else {
            if (i     < N) { v0 = g_deg[i];     g_deg[i]     = 0; }
            if (i + 1 < N) { v1 = g_deg[i + 1]; g_deg[i + 1] = 0; }
            if (i + 2 < N) { v2 = g_deg[i + 2]; g_deg[i + 2] = 0; }
        }
        int s = v0 + v1 + v2 + v3;
        int xi = s;
#pragma unroll
        for (int o = 1; o < 32; o <<= 1) {
            int t = __shfl_up_sync(0xFFFFFFFFu, xi, o);
            if (lane >= o) xi += t;
        }
        if (lane == 31) wsum[wid] = xi;
        __syncthreads();
        if (wid == 0) {
            int y = wsum[lane];
#pragma unroll
            for (int o = 1; o < 32; o <<= 1) {
                int t = __shfl_up_sync(0xFFFFFFFFu, y, o);
                if (lane >= o) y += t;
            }
            wsum[lane] = y;
        }
        __syncthreads();
        int excl = xi - s + (wid ? wsum[wid - 1] : 0) + carry_s;
        int o0 = excl, o1 = o0 + v0, o2 = o1 + v1, o3 = o2 + v2;
        if (i     < N) { g_offs[i]     = o0; g_cursor[i]     = o0; }
        if (i + 1 < N) { g_offs[i + 1] = o1; g_cursor[i + 1] = o1; }
        if (i + 2 < N) { g_offs[i + 2] = o2; g_cursor[i + 2] = o2; }
        if (i + 3 < N) { g_offs[i + 3] = o3; g_cursor[i + 3] = o3; }
        __syncthreads();
        if (tid == 0) carry_s += wsum[31];
        __syncthreads();
    }
    if (tid == 0) g_offs[N] = carry_s;
}

// ---------------------------------------------------------------------------
// Scatter + score: writes packed {src, leaky(sd[dst]+ss[src])} per edge.
// ---------------------------------------------------------------------------
__global__ void scatter_kernel(const int* __restrict__ src,
                               const int* __restrict__ dst, int E) {
    int i = blockIdx.x * blockDim.x + threadIdx.x;
    if (i < E) {
        int s = src[i];
        int d = dst[i];
        float sc = g_sd[d] + g_ss[s];
        sc = (sc >= 0.f) ? sc : 0.01f * sc;
        int p = atomicAdd(&g_cursor[d], 1);
        g_edge[p] = make_int2(s, __float_as_int(sc));
    }
}

// ---------------------------------------------------------------------------
// Aggregate: one warp per destination, single pass, online softmax.
// Edges in chunks of 32: lanes load (src, score) + compute exp in parallel;
// running max/scale flash-style; then shuffle-broadcast accumulate loop:
// 2x SHFL + LDG.64 + FMA2 per edge.
// ---------------------------------------------------------------------------
__global__ void aggregate_kernel(float* __restrict__ out, int N) {
    int warp = (blockIdx.x * blockDim.x + threadIdx.x) >> 5;
    int lane = threadIdx.x & 31;
    if (warp >= N) return;
    int beg = g_offs[warp], end = g_offs[warp + 1];

    const float2* hb = (const float2*)g_h;
    unsigned long long acc = 0ULL;
    float esum = 0.f;
    float m = -INFINITY;

    for (int j0 = beg; j0 < end; j0 += 32) {
        int cnt = min(32, end - j0);
        int sidx = 0;
        float sc = -INFINITY;
        if (lane < cnt) {
            int2 ed = g_edge[j0 + lane];
            sidx = ed.x;
            sc = __int_as_float(ed.y);
        }
        // chunk max
        float cm = sc;
#pragma unroll
        for (int o = 16; o; o >>= 1)
            cm = fmaxf(cm, __shfl_xor_sync(0xFFFFFFFFu, cm, o));
        float nm = fmaxf(m, cm);
        float scale = __expf(m - nm);          // 0 on first chunk (m=-inf)
        float ev = (lane < cnt) ? __expf(sc - nm) : 0.f;
        // chunk sum
        float cs = ev;
#pragma unroll
        for (int o = 16; o; o >>= 1)
            cs += __shfl_xor_sync(0xFFFFFFFFu, cs, o);
        esum = esum * scale + cs;
        mul2(acc, pack2(scale, scale));
        m = nm;

#pragma unroll 4
        for (int t = 0; t < cnt; ++t) {
            float e  = __shfl_sync(0xFFFFFFFFu, ev, t);
            int   si = __shfl_sync(0xFFFFFFFFu, sidx, t);
            float2 hvv = hb[(size_t)si * 32 + lane];
            fma2(acc, *(unsigned long long*)&hvv, pack2(e, e));
        }
    }

    float inv = (end > beg) ? (1.0f / esum) : 0.0f;
    float2 hd = hb[(size_t)warp * 32 + lane];
    float2 af = unpack2(acc);
    float2 o;
    o.x = hd.x - af.x * inv;
    o.y = hd.y - af.y * inv;
    o.x = o.x > 0.f ? o.x : 0.f;
    o.y = o.y > 0.f ? o.y : 0.f;
    ((float2*)out)[(size_t)warp * 32 + lane] = o;
}

// ---------------------------------------------------------------------------
extern "C" void kernel_launch(void* const* d_in, const int* in_sizes, int n_in,
                              void* d_out, int out_size)
{
    const float* x   = (const float*)d_in[0];   // [N, 256]
    const float* W1  = (const float*)d_in[1];   // [64, 256]
    const float* W2  = (const float*)d_in[2];   // [64, 64]
    const float* a   = (const float*)d_in[3];   // [128, 1]
    const int*   src = (const int*)d_in[4];     // [E]
    const int*   dst = (const int*)d_in[5];     // [E]
    float* out = (float*)d_out;

    int N = in_sizes[0] / 256;
    int E = in_sizes[4];

    cudaFuncSetAttribute(fused_mlp_hist_kernel,
                         cudaFuncAttributeMaxDynamicSharedMemorySize,
                         SMEM_FLOATS * 4);

    int mlp_blocks = (N + 127) / 128;
    fused_mlp_hist_kernel<<<HIST_BLOCKS + mlp_blocks, 256, SMEM_FLOATS * 4>>>(
        x, W1, W2, a, dst, N, E);

    scan_kernel<<<1, 1024>>>(N);
    scatter_kernel<<<(E + 255) / 256, 256>>>(src, dst, E);
    aggregate_kernel<<<(N * 32 + 255) / 256, 256>>>(out, N);
}

// round 5
// speedup vs baseline: 1.5073x; 1.5073x over previous
#include <cuda_runtime.h>
#include <cuda_bf16.h>
#include <math.h>

#define MAX_N 50000
#define MAX_E 800000
#define HIST_BLOCKS 128

// Scratch (device globals — zero-initialized at load)
__device__ float g_h[MAX_N * 64];
__device__ float g_sd[MAX_N];
__device__ float g_ss[MAX_N];
__device__ int   g_deg[MAX_N];          // re-zeroed by scan_kernel each call
__device__ int   g_offs[MAX_N + 1];
__device__ int   g_cursor[MAX_N];
__device__ int2  g_edge[MAX_E];         // {src, leaky-score bits}
__device__ float g_escore[MAX_E];       // exp(score - m) per edge

// ---------------------------------------------------------------------------
// f32x2 packed-math helpers (sm_103a)
// ---------------------------------------------------------------------------
__device__ __forceinline__ unsigned long long pack2(float x, float y) {
    unsigned long long r;
    asm("mov.b64 %0, {%1, %2};" : "=l"(r) : "f"(x), "f"(y));
    return r;
}
__device__ __forceinline__ float2 unpack2(unsigned long long v) {
    float2 f;
    asm("mov.b64 {%0, %1}, %2;" : "=f"(f.x), "=f"(f.y) : "l"(v));
    return f;
}
__device__ __forceinline__ void fma2(unsigned long long& d,
                                     unsigned long long a,
                                     unsigned long long b) {
    asm("fma.rn.f32x2 %0, %1, %2, %0;" : "+l"(d) : "l"(a), "l"(b));
}

// ---------------------------------------------------------------------------
// Fused: hist blocks do degree histogram; MLP blocks compute
// h = relu(relu(x@W1^T)@W2^T) for 128 rows + dots sd/ss.  (R3 form.)
// ---------------------------------------------------------------------------
#define AS_OFF 0
#define BS_OFF 4224
#define W2_OFF 0
#define ZS_OFF 6272
#define SMEM_FLOATS (ZS_OFF + 64 * 132)   // 14720 floats = 58880 B

__global__ __launch_bounds__(256, 2)
void fused_mlp_hist_kernel(const float* __restrict__ x,
                           const float* __restrict__ W1,
                           const float* __restrict__ W2,
                           const float* __restrict__ a,
                           const int* __restrict__ dst,
                           int N, int E)
{
    const int tid = threadIdx.x;

    if (blockIdx.x < HIST_BLOCKS) {
        int stride = HIST_BLOCKS * 256;
        for (int i = blockIdx.x * 256 + tid; i < E; i += stride)
            atomicAdd(&g_deg[dst[i]], 1);
        return;
    }

    extern __shared__ float smem[];
    float* As  = smem + AS_OFF;
    float* Bs  = smem + BS_OFF;
    float* W2s = smem + W2_OFF;
    float* zs  = smem + ZS_OFF;

    const int tx   = tid & 15;
    const int ty   = tid >> 4;
    const int row0 = (blockIdx.x - HIST_BLOCKS) * 128;

    float a_d[4], a_s[4];
#pragma unroll
    for (int j = 0; j < 4; j++) {
        a_d[j] = a[tx * 4 + j];
        a_s[j] = a[64 + tx * 4 + j];
    }

    // ------------------ Phase A: z = relu(x @ W1^T), K=256 ------------------
    unsigned long long acc[4][4];
#pragma unroll
    for (int p = 0; p < 4; p++)
#pragma unroll
        for (int j = 0; j < 4; j++) acc[p][j] = 0ULL;

    for (int kb = 0; kb < 256; kb += 32) {
#pragma unroll
        for (int q = 0; q < 4; q++) {
            int idx = tid + q * 256;
            int r   = idx >> 3;
            int k4  = idx & 7;
            int grow = row0 + r;
            float4 v = make_float4(0.f, 0.f, 0.f, 0.f);
            if (grow < N)
                v = *(const float4*)(x + (size_t)grow * 256 + kb + k4 * 4);
            As[(k4 * 4 + 0) * 132 + r] = v.x;
            As[(k4 * 4 + 1) * 132 + r] = v.y;
            As[(k4 * 4 + 2) * 132 + r] = v.z;
            As[(k4 * 4 + 3) * 132 + r] = v.w;
        }
#pragma unroll
        for (int q = 0; q < 2; q++) {
            int idx = tid + q * 256;
            int c   = idx >> 3;
            int k4  = idx & 7;
            float4 w = *(const float4*)(W1 + (size_t)c * 256 + kb + k4 * 4);
            Bs[(k4 * 4 + 0) * 64 + c] = w.x;
            Bs[(k4 * 4 + 1) * 64 + c] = w.y;
            Bs[(k4 * 4 + 2) * 64 + c] = w.z;
            Bs[(k4 * 4 + 3) * 64 + c] = w.w;
        }
        __syncthreads();

#pragma unroll 8
        for (int k = 0; k < 32; k++) {
            ulonglong2 av0 = *(const ulonglong2*)(As + k * 132 + ty * 8);
            ulonglong2 av1 = *(const ulonglong2*)(As + k * 132 + ty * 8 + 4);
            float4 bv = *(const float4*)(Bs + k * 64 + tx * 4);
            unsigned long long ap[4] = {av0.x, av0.y, av1.x, av1.y};
            unsigned long long bp[4] = {pack2(bv.x, bv.x), pack2(bv.y, bv.y),
                                        pack2(bv.z, bv.z), pack2(bv.w, bv.w)};
#pragma unroll
            for (int p = 0; p < 4; p++)
#pragma unroll
                for (int j = 0; j < 4; j++)
                    fma2(acc[p][j], ap[p], bp[j]);
        }
        __syncthreads();
    }

    // relu z -> zs (k-major), load W2 into freed region
#pragma unroll
    for (int p = 0; p < 4; p++)
#pragma unroll
        for (int j = 0; j < 4; j++) {
            float2 f = unpack2(acc[p][j]);
            f.x = f.x > 0.f ? f.x : 0.f;
            f.y = f.y > 0.f ? f.y : 0.f;
            int rl = ty * 8 + p * 2;
            int c  = tx * 4 + j;
            zs[c * 132 + rl]     = f.x;
            zs[c * 132 + rl + 1] = f.y;
        }
#pragma unroll
    for (int q = 0; q < 16; q++) {
        int idx = tid + q * 256;
        int c = idx >> 6;
        int k = idx & 63;
        W2s[k * 68 + c] = W2[idx];
    }
    __syncthreads();

    // ------------------ Phase B: h = relu(z @ W2^T), K=64 -------------------
    unsigned long long hacc[4][4];
#pragma unroll
    for (int p = 0; p < 4; p++)
#pragma unroll
        for (int j = 0; j < 4; j++) hacc[p][j] = 0ULL;

#pragma unroll 8
    for (int k = 0; k < 64; k++) {
        ulonglong2 av0 = *(const ulonglong2*)(zs + k * 132 + ty * 8);
        ulonglong2 av1 = *(const ulonglong2*)(zs + k * 132 + ty * 8 + 4);
        float4 bv = *(const float4*)(W2s + k * 68 + tx * 4);
        unsigned long long ap[4] = {av0.x, av0.y, av1.x, av1.y};
        unsigned long long bp[4] = {pack2(bv.x, bv.x), pack2(bv.y, bv.y),
                                    pack2(bv.z, bv.z), pack2(bv.w, bv.w)};
#pragma unroll
        for (int p = 0; p < 4; p++)
#pragma unroll
            for (int j = 0; j < 4; j++)
                fma2(hacc[p][j], ap[p], bp[j]);
    }

    // ------------------ Epilogue: relu, store h, dots -----------------------
    float hv[4][4][2];
    float pd[8], ps[8];
#pragma unroll
    for (int r = 0; r < 8; r++) { pd[r] = 0.f; ps[r] = 0.f; }

#pragma unroll
    for (int p = 0; p < 4; p++)
#pragma unroll
        for (int j = 0; j < 4; j++) {
            float2 f = unpack2(hacc[p][j]);
            f.x = f.x > 0.f ? f.x : 0.f;
            f.y = f.y > 0.f ? f.y : 0.f;
            hv[p][j][0] = f.x;
            hv[p][j][1] = f.y;
            pd[p * 2 + 0] = fmaf(f.x, a_d[j], pd[p * 2 + 0]);
            pd[p * 2 + 1] = fmaf(f.y, a_d[j], pd[p * 2 + 1]);
            ps[p * 2 + 0] = fmaf(f.x, a_s[j], ps[p * 2 + 0]);
            ps[p * 2 + 1] = fmaf(f.y, a_s[j], ps[p * 2 + 1]);
        }

#pragma unroll
    for (int p = 0; p < 4; p++)
#pragma unroll
        for (int q = 0; q < 2; q++) {
            int row = row0 + ty * 8 + p * 2 + q;
            if (row < N) {
                float4 o = make_float4(hv[p][0][q], hv[p][1][q],
                                       hv[p][2][q], hv[p][3][q]);
                *(float4*)(g_h + (size_t)row * 64 + tx * 4) = o;
            }
        }

#pragma unroll
    for (int off = 8; off; off >>= 1)
#pragma unroll
        for (int r = 0; r < 8; r++) {
            pd[r] += __shfl_xor_sync(0xFFFFFFFFu, pd[r], off);
            ps[r] += __shfl_xor_sync(0xFFFFFFFFu, ps[r], off);
        }
    if (tx == 0) {
#pragma unroll
        for (int r = 0; r < 8; r++) {
            int row = row0 + ty * 8 + r;
            if (row < N) { g_sd[row] = pd[r]; g_ss[row] = ps[r]; }
        }
    }
}

// ---------------------------------------------------------------------------
// Scan: exclusive prefix of g_deg -> g_offs/g_cursor; re-zero g_deg.
// ---------------------------------------------------------------------------
__global__ void scan_kernel(int N) {
    __shared__ int wsum[32];
    __shared__ int carry_s;
    int tid = threadIdx.x, lane = tid & 31, wid = tid >> 5;
    if (tid == 0) carry_s = 0;
    __syncthreads();
    for (int base = 0; base < N; base += 4096) {
        int i = base + tid * 4;
        int v0 = 0, v1 = 0, v2 = 0, v3 = 0;
        if (i + 3 < N) {
            int4 t = *(const int4*)&g_deg[i];
            v0 = t.x; v1 = t.y; v2 = t.z; v3 = t.w;
            *(int4*)&g_deg[i] = make_int4(0, 0, 0, 0);
        } else {
            if (i     < N) { v0 = g_deg[i];     g_deg[i]     = 0; }
            if (i + 1 < N) { v1 = g_deg[i + 1]; g_deg[i + 1] = 0; }
            if (i + 2 < N) { v2 = g_deg[i + 2]; g_deg[i + 2] = 0; }
        }
        int s = v0 + v1 + v2 + v3;
        int xi = s;
#pragma unroll
        for (int o = 1; o < 32; o <<= 1) {
            int t = __shfl_up_sync(0xFFFFFFFFu, xi, o);
            if (lane >= o) xi += t;
        }
        if (lane == 31) wsum[wid] = xi;
        __syncthreads();
        if (wid == 0) {
            int y = wsum[lane];
#pragma unroll
            for (int o = 1; o < 32; o <<= 1) {
                int t = __shfl_up_sync(0xFFFFFFFFu, y, o);
                if (lane >= o) y += t;
            }
            wsum[lane] = y;
        }
        __syncthreads();
        int excl = xi - s + (wid ? wsum[wid - 1] : 0) + carry_s;
        int o0 = excl, o1 = o0 + v0, o2 = o1 + v1, o3 = o2 + v2;
        if (i     < N) { g_offs[i]     = o0; g_cursor[i]     = o0; }
        if (i + 1 < N) { g_offs[i + 1] = o1; g_cursor[i + 1] = o1; }
        if (i + 2 < N) { g_offs[i + 2] = o2; g_cursor[i + 2] = o2; }
        if (i + 3 < N) { g_offs[i + 3] = o3; g_cursor[i + 3] = o3; }
        __syncthreads();
        if (tid == 0) carry_s += wsum[31];
        __syncthreads();
    }
    if (tid == 0) g_offs[N] = carry_s;
}

// ---------------------------------------------------------------------------
// Scatter + score: writes packed {src, leaky(sd[dst]+ss[src])} per edge.
// ---------------------------------------------------------------------------
__global__ void scatter_kernel(const int* __restrict__ src,
                               const int* __restrict__ dst, int E) {
    int i = blockIdx.x * blockDim.x + threadIdx.x;
    if (i < E) {
        int s = src[i];
        int d = dst[i];
        float sc = g_sd[d] + g_ss[s];
        sc = (sc >= 0.f) ? sc : 0.01f * sc;
        int p = atomicAdd(&g_cursor[d], 1);
        g_edge[p] = make_int2(s, __float_as_int(sc));
    }
}

// ---------------------------------------------------------------------------
// Aggregate: one warp per destination node.
// Sweep 1 (lane-parallel): max of stashed scores.
// Sweep 2 (lane-parallel): e = exp(sc-m) -> g_escore (contiguous), esum via
//          one warp reduction.
// Sweep 3 (uniform, 2 edges/iter): int4 load of g_edge pairs + float2 escore,
//          h-row LDG.64 + fma2 per edge. No SHFL, no MUFU in this loop.
// ---------------------------------------------------------------------------
__global__ void aggregate_kernel(float* __restrict__ out, int N) {
    int warp = (blockIdx.x * blockDim.x + threadIdx.x) >> 5;
    int lane = threadIdx.x & 31;
    if (warp >= N) return;
    int beg = g_offs[warp], end = g_offs[warp + 1];

    // sweep 1: max
    float m = -INFINITY;
    for (int j = beg + lane; j < end; j += 32)
        m = fmaxf(m, __int_as_float(g_edge[j].y));
#pragma unroll
    for (int o = 16; o; o >>= 1)
        m = fmaxf(m, __shfl_xor_sync(0xFFFFFFFFu, m, o));

    // sweep 2: exp + stash + esum
    float esum = 0.f;
    for (int j = beg + lane; j < end; j += 32) {
        float e = __expf(__int_as_float(g_edge[j].y) - m);
        g_escore[j] = e;
        esum += e;
    }
#pragma unroll
    for (int o = 16; o; o >>= 1)
        esum += __shfl_xor_sync(0xFFFFFFFFu, esum, o);
    __syncwarp();

    // sweep 3: uniform accumulate
    const float2* hb = (const float2*)g_h;
    unsigned long long acc = 0ULL;
    int j = beg;
    if ((j & 1) && j < end) {                 // align to int4 boundary
        int2 ed = g_edge[j];
        float e = g_escore[j];
        float2 hvv = hb[(size_t)ed.x * 32 + lane];
        fma2(acc, *(unsigned long long*)&hvv, pack2(e, e));
        ++j;
    }
    for (; j + 2 <= end; j += 2) {
        int4  ed = *(const int4*)&g_edge[j];      // {s0,sc0,s1,sc1}
        float2 ee = *(const float2*)&g_escore[j];
        float2 h0 = hb[(size_t)ed.x * 32 + lane];
        float2 h1 = hb[(size_t)ed.z * 32 + lane];
        fma2(acc, *(unsigned long long*)&h0, pack2(ee.x, ee.x));
        fma2(acc, *(unsigned long long*)&h1, pack2(ee.y, ee.y));
    }
    if (j < end) {
        int2 ed = g_edge[j];
        float e = g_escore[j];
        float2 hvv = hb[(size_t)ed.x * 32 + lane];
        fma2(acc, *(unsigned long long*)&hvv, pack2(e, e));
    }

    float inv = (end > beg) ? (1.0f / esum) : 0.0f;
    float2 hd = hb[(size_t)warp * 32 + lane];
    float2 af = unpack2(acc);
    float2 o;
    o.x = hd.x - af.x * inv;
    o.y = hd.y - af.y * inv;
    o.x = o.x > 0.f ? o.x : 0.f;
    o.y = o.y > 0.f ? o.y : 0.f;
    ((float2*)out)[(size_t)warp * 32 + lane] = o;
}

// ---------------------------------------------------------------------------
extern "C" void kernel_launch(void* const* d_in, const int* in_sizes, int n_in,
                              void* d_out, int out_size)
{
    const float* x   = (const float*)d_in[0];   // [N, 256]
    const float* W1  = (const float*)d_in[1];   // [64, 256]
    const float* W2  = (const float*)d_in[2];   // [64, 64]
    const float* a   = (const float*)d_in[3];   // [128, 1]
    const int*   src = (const int*)d_in[4];     // [E]
    const int*   dst = (const int*)d_in[5];     // [E]
    float* out = (float*)d_out;

    int N = in_sizes[0] / 256;
    int E = in_sizes[4];

    cudaFuncSetAttribute(fused_mlp_hist_kernel,
                         cudaFuncAttributeMaxDynamicSharedMemorySize,
                         SMEM_FLOATS * 4);

    int mlp_blocks = (N + 127) / 128;
    fused_mlp_hist_kernel<<<HIST_BLOCKS + mlp_blocks, 256, SMEM_FLOATS * 4>>>(
        x, W1, W2, a, dst, N, E);

    scan_kernel<<<1, 1024>>>(N);
    scatter_kernel<<<(E + 255) / 256, 256>>>(src, dst, E);
    aggregate_kernel<<<(N * 32 + 255) / 256, 256>>>(out, N);
}

// round 6
// speedup vs baseline: 1.9674x; 1.3052x over previous
#include <cuda_runtime.h>
#include <cuda_bf16.h>
#include <math.h>

#define MAX_N 50000
#define MAX_E 800000
#define HIST_BLOCKS 128
#define SCAN_CHUNK 512               // ints per scan block
#define MAX_SCAN_BLOCKS ((MAX_N + SCAN_CHUNK - 1) / SCAN_CHUNK)

// Scratch (device globals — zero-initialized at load)
__device__ float g_h[MAX_N * 64];
__device__ float g_sd[MAX_N];
__device__ float g_ss[MAX_N];
__device__ int   g_deg[MAX_N];          // re-zeroed by scan phase 3 each call
__device__ int   g_offs[MAX_N + 1];
__device__ int   g_cursor[MAX_N];
__device__ int2  g_edge[MAX_E];         // {src, leaky-score bits}
__device__ float g_escore[MAX_E];       // exp(score - m) per edge
__device__ int   g_bsum[MAX_SCAN_BLOCKS];
__device__ int   g_bpre[MAX_SCAN_BLOCKS];

// ---------------------------------------------------------------------------
// f32x2 packed-math helpers (sm_103a)
// ---------------------------------------------------------------------------
__device__ __forceinline__ unsigned long long pack2(float x, float y) {
    unsigned long long r;
    asm("mov.b64 %0, {%1, %2};" : "=l"(r) : "f"(x), "f"(y));
    return r;
}
__device__ __forceinline__ float2 unpack2(unsigned long long v) {
    float2 f;
    asm("mov.b64 {%0, %1}, %2;" : "=f"(f.x), "=f"(f.y) : "l"(v));
    return f;
}
__device__ __forceinline__ void fma2(unsigned long long& d,
                                     unsigned long long a,
                                     unsigned long long b) {
    asm("fma.rn.f32x2 %0, %1, %2, %0;" : "+l"(d) : "l"(a), "l"(b));
}

// ---------------------------------------------------------------------------
// Fused: MLP blocks first (wave-1 pure MLP), hist blocks at the END of the
// grid so they pack into the MLP tail wave.
// MLP: h = relu(relu(x@W1^T)@W2^T) for 128 rows + dots sd/ss.
// ---------------------------------------------------------------------------
#define AS_OFF 0
#define BS_OFF 4224
#define W2_OFF 0
#define ZS_OFF 6272
#define SMEM_FLOATS (ZS_OFF + 64 * 132)   // 14720 floats = 58880 B

__global__ __launch_bounds__(256, 2)
void fused_mlp_hist_kernel(const float* __restrict__ x,
                           const float* __restrict__ W1,
                           const float* __restrict__ W2,
                           const float* __restrict__ a,
                           const int* __restrict__ dst,
                           int N, int E, int mlp_blocks)
{
    const int tid = threadIdx.x;

    if (blockIdx.x >= mlp_blocks) {          // ---- hist role (tail blocks)
        int hb = blockIdx.x - mlp_blocks;
        int stride = HIST_BLOCKS * 256;
        for (int i = hb * 256 + tid; i < E; i += stride)
            atomicAdd(&g_deg[dst[i]], 1);
        return;
    }

    extern __shared__ float smem[];
    float* As  = smem + AS_OFF;
    float* Bs  = smem + BS_OFF;
    float* W2s = smem + W2_OFF;
    float* zs  = smem + ZS_OFF;

    const int tx   = tid & 15;
    const int ty   = tid >> 4;
    const int row0 = blockIdx.x * 128;

    float a_d[4], a_s[4];
#pragma unroll
    for (int j = 0; j < 4; j++) {
        a_d[j] = a[tx * 4 + j];
        a_s[j] = a[64 + tx * 4 + j];
    }

    // ------------------ Phase A: z = relu(x @ W1^T), K=256 ------------------
    unsigned long long acc[4][4];
#pragma unroll
    for (int p = 0; p < 4; p++)
#pragma unroll
        for (int j = 0; j < 4; j++) acc[p][j] = 0ULL;

    for (int kb = 0; kb < 256; kb += 32) {
#pragma unroll
        for (int q = 0; q < 4; q++) {
            int idx = tid + q * 256;
            int r   = idx >> 3;
            int k4  = idx & 7;
            int grow = row0 + r;
            float4 v = make_float4(0.f, 0.f, 0.f, 0.f);
            if (grow < N)
                v = *(const float4*)(x + (size_t)grow * 256 + kb + k4 * 4);
            As[(k4 * 4 + 0) * 132 + r] = v.x;
            As[(k4 * 4 + 1) * 132 + r] = v.y;
            As[(k4 * 4 + 2) * 132 + r] = v.z;
            As[(k4 * 4 + 3) * 132 + r] = v.w;
        }
#pragma unroll
        for (int q = 0; q < 2; q++) {
            int idx = tid + q * 256;
            int c   = idx >> 3;
            int k4  = idx & 7;
            float4 w = *(const float4*)(W1 + (size_t)c * 256 + kb + k4 * 4);
            Bs[(k4 * 4 + 0) * 64 + c] = w.x;
            Bs[(k4 * 4 + 1) * 64 + c] = w.y;
            Bs[(k4 * 4 + 2) * 64 + c] = w.z;
            Bs[(k4 * 4 + 3) * 64 + c] = w.w;
        }
        __syncthreads();

#pragma unroll 8
        for (int k = 0; k < 32; k++) {
            ulonglong2 av0 = *(const ulonglong2*)(As + k * 132 + ty * 8);
            ulonglong2 av1 = *(const ulonglong2*)(As + k * 132 + ty * 8 + 4);
            float4 bv = *(const float4*)(Bs + k * 64 + tx * 4);
            unsigned long long ap[4] = {av0.x, av0.y, av1.x, av1.y};
            unsigned long long bp[4] = {pack2(bv.x, bv.x), pack2(bv.y, bv.y),
                                        pack2(bv.z, bv.z), pack2(bv.w, bv.w)};
#pragma unroll
            for (int p = 0; p < 4; p++)
#pragma unroll
                for (int j = 0; j < 4; j++)
                    fma2(acc[p][j], ap[p], bp[j]);
        }
        __syncthreads();
    }

    // relu z -> zs (k-major), load W2 into freed region
#pragma unroll
    for (int p = 0; p < 4; p++)
#pragma unroll
        for (int j = 0; j < 4; j++) {
            float2 f = unpack2(acc[p][j]);
            f.x = f.x > 0.f ? f.x : 0.f;
            f.y = f.y > 0.f ? f.y : 0.f;
            int rl = ty * 8 + p * 2;
            int c  = tx * 4 + j;
            zs[c * 132 + rl]     = f.x;
            zs[c * 132 + rl + 1] = f.y;
        }
#pragma unroll
    for (int q = 0; q < 16; q++) {
        int idx = tid + q * 256;
        int c = idx >> 6;
        int k = idx & 63;
        W2s[k * 68 + c] = W2[idx];
    }
    __syncthreads();

    // ------------------ Phase B: h = relu(z @ W2^T), K=64 -------------------
    unsigned long long hacc[4][4];
#pragma unroll
    for (int p = 0; p < 4; p++)
#pragma unroll
        for (int j = 0; j < 4; j++) hacc[p][j] = 0ULL;

#pragma unroll 8
    for (int k = 0; k < 64; k++) {
        ulonglong2 av0 = *(const ulonglong2*)(zs + k * 132 + ty * 8);
        ulonglong2 av1 = *(const ulonglong2*)(zs + k * 132 + ty * 8 + 4);
        float4 bv = *(const float4*)(W2s + k * 68 + tx * 4);
        unsigned long long ap[4] = {av0.x, av0.y, av1.x, av1.y};
        unsigned long long bp[4] = {pack2(bv.x, bv.x), pack2(bv.y, bv.y),
                                    pack2(bv.z, bv.z), pack2(bv.w, bv.w)};
#pragma unroll
        for (int p = 0; p < 4; p++)
#pragma unroll
            for (int j = 0; j < 4; j++)
                fma2(hacc[p][j], ap[p], bp[j]);
    }

    // ------------------ Epilogue: relu, store h, dots -----------------------
    float hv[4][4][2];
    float pd[8], ps[8];
#pragma unroll
    for (int r = 0; r < 8; r++) { pd[r] = 0.f; ps[r] = 0.f; }

#pragma unroll
    for (int p = 0; p < 4; p++)
#pragma unroll
        for (int j = 0; j < 4; j++) {
            float2 f = unpack2(hacc[p][j]);
            f.x = f.x > 0.f ? f.x : 0.f;
            f.y = f.y > 0.f ? f.y : 0.f;
            hv[p][j][0] = f.x;
            hv[p][j][1] = f.y;
            pd[p * 2 + 0] = fmaf(f.x, a_d[j], pd[p * 2 + 0]);
            pd[p * 2 + 1] = fmaf(f.y, a_d[j], pd[p * 2 + 1]);
            ps[p * 2 + 0] = fmaf(f.x, a_s[j], ps[p * 2 + 0]);
            ps[p * 2 + 1] = fmaf(f.y, a_s[j], ps[p * 2 + 1]);
        }

#pragma unroll
    for (int p = 0; p < 4; p++)
#pragma unroll
        for (int q = 0; q < 2; q++) {
            int row = row0 + ty * 8 + p * 2 + q;
            if (row < N) {
                float4 o = make_float4(hv[p][0][q], hv[p][1][q],
                                       hv[p][2][q], hv[p][3][q]);
                *(float4*)(g_h + (size_t)row * 64 + tx * 4) = o;
            }
        }

#pragma unroll
    for (int off = 8; off; off >>= 1)
#pragma unroll
        for (int r = 0; r < 8; r++) {
            pd[r] += __shfl_xor_sync(0xFFFFFFFFu, pd[r], off);
            ps[r] += __shfl_xor_sync(0xFFFFFFFFu, ps[r], off);
        }
    if (tx == 0) {
#pragma unroll
        for (int r = 0; r < 8; r++) {
            int row = row0 + ty * 8 + r;
            if (row < N) { g_sd[row] = pd[r]; g_ss[row] = ps[r]; }
        }
    }
}

// ---------------------------------------------------------------------------
// Multi-block scan, 3 phases.
// Phase 1: per-block sum of SCAN_CHUNK degrees.
// Phase 2: single small block scans the ~98 block sums (exclusive).
// Phase 3: per-block local exclusive scan + write offs/cursor + zero g_deg.
// ---------------------------------------------------------------------------
__global__ void scan_sum_kernel(int N) {
    __shared__ int ws[8];
    int b = blockIdx.x, tid = threadIdx.x;
    int lane = tid & 31, wid = tid >> 5;
    int i = b * SCAN_CHUNK + tid * 2;
    int v = 0;
    if (i + 1 < N)      v = g_deg[i] + g_deg[i + 1];
    else if (i < N)     v = g_deg[i];
#pragma unroll
    for (int o = 16; o; o >>= 1)
        v += __shfl_xor_sync(0xFFFFFFFFu, v, o);
    if (lane == 0) ws[wid] = v;
    __syncthreads();
    if (tid == 0) {
        int s = 0;
#pragma unroll
        for (int w = 0; w < 8; w++) s += ws[w];
        g_bsum[b] = s;
    }
}

__global__ void scan_mid_kernel(int nblocks, int E) {
    __shared__ int wtot[4];
    int tid = threadIdx.x;          // 128 threads
    int lane = tid & 31, wid = tid >> 5;
    int v = (tid < nblocks) ? g_bsum[tid] : 0;
    int x = v;
#pragma unroll
    for (int o = 1; o < 32; o <<= 1) {
        int t = __shfl_up_sync(0xFFFFFFFFu, x, o);
        if (lane >= o) x += t;
    }
    if (lane == 31) wtot[wid] = x;
    __syncthreads();
    int wpre = 0;
#pragma unroll
    for (int w = 0; w < 4; w++)
        if (w < wid) wpre += wtot[w];
    if (tid < nblocks) g_bpre[tid] = x - v + wpre;
    if (tid == 0) g_offs[MAX_N] = 0;   // placeholder (real N slot set in phase 3)
}

__global__ void scan_local_kernel(int N, int E) {
    __shared__ int wsum[8];
    int b = blockIdx.x, tid = threadIdx.x;
    int lane = tid & 31, wid = tid >> 5;
    int i = b * SCAN_CHUNK + tid * 2;
    int v0 = 0, v1 = 0;
    if (i + 1 < N) {
        int2 t = *(const int2*)&g_deg[i];
        v0 = t.x; v1 = t.y;
        *(int2*)&g_deg[i] = make_int2(0, 0);
    } else if (i < N) {
        v0 = g_deg[i]; g_deg[i] = 0;
    }
    int s = v0 + v1;
    int x = s;
#pragma unroll
    for (int o = 1; o < 32; o <<= 1) {
        int t = __shfl_up_sync(0xFFFFFFFFu, x, o);
        if (lane >= o) x += t;
    }
    if (lane == 31) wsum[wid] = x;
    __syncthreads();
    int wpre = 0;
#pragma unroll
    for (int w = 0; w < 8; w++)
        if (w < wid) wpre += wsum[w];
    int excl = x - s + wpre + g_bpre[b];
    if (i < N) {
        g_offs[i] = excl;  g_cursor[i] = excl;
        if (i + 1 < N) { g_offs[i + 1] = excl + v0; g_cursor[i + 1] = excl + v0; }
    }
    if (b == 0 && tid == 0) g_offs[N] = E;
}

// ---------------------------------------------------------------------------
// Scatter + score: writes packed {src, leaky(sd[dst]+ss[src])} per edge.
// ---------------------------------------------------------------------------
__global__ void scatter_kernel(const int* __restrict__ src,
                               const int* __restrict__ dst, int E) {
    int i = blockIdx.x * blockDim.x + threadIdx.x;
    if (i < E) {
        int s = src[i];
        int d = dst[i];
        float sc = g_sd[d] + g_ss[s];
        sc = (sc >= 0.f) ? sc : 0.01f * sc;
        int p = atomicAdd(&g_cursor[d], 1);
        g_edge[p] = make_int2(s, __float_as_int(sc));
    }
}

// ---------------------------------------------------------------------------
// Aggregate: one warp per destination node. 3 sweeps; sweep 3 uses dual
// accumulators + 4-edge unroll (4 h-row loads in flight, 2 FMA2 chains).
// ---------------------------------------------------------------------------
__global__ void aggregate_kernel(float* __restrict__ out, int N) {
    int warp = (blockIdx.x * blockDim.x + threadIdx.x) >> 5;
    int lane = threadIdx.x & 31;
    if (warp >= N) return;
    int beg = g_offs[warp], end = g_offs[warp + 1];

    // sweep 1: max
    float m = -INFINITY;
    for (int j = beg + lane; j < end; j += 32)
        m = fmaxf(m, __int_as_float(g_edge[j].y));
#pragma unroll
    for (int o = 16; o; o >>= 1)
        m = fmaxf(m, __shfl_xor_sync(0xFFFFFFFFu, m, o));

    // sweep 2: exp + stash + esum
    float esum = 0.f;
    for (int j = beg + lane; j < end; j += 32) {
        float e = __expf(__int_as_float(g_edge[j].y) - m);
        g_escore[j] = e;
        esum += e;
    }
#pragma unroll
    for (int o = 16; o; o >>= 1)
        esum += __shfl_xor_sync(0xFFFFFFFFu, esum, o);
    __syncwarp();

    // sweep 3: uniform accumulate, dual accumulators
    const float2* hb = (const float2*)g_h;
    unsigned long long accA = 0ULL, accB = 0ULL;
    int j = beg;
    if ((j & 1) && j < end) {
        int2 ed = g_edge[j];
        float e = g_escore[j];
        float2 hvv = hb[(size_t)ed.x * 32 + lane];
        fma2(accA, *(unsigned long long*)&hvv, pack2(e, e));
        ++j;
    }
    for (; j + 4 <= end; j += 4) {
        int4   e0 = *(const int4*)&g_edge[j];
        int4   e1 = *(const int4*)&g_edge[j + 2];
        float2 s0 = *(const float2*)&g_escore[j];
        float2 s1 = *(const float2*)&g_escore[j + 2];
        float2 h0 = hb[(size_t)e0.x * 32 + lane];
        float2 h1 = hb[(size_t)e0.z * 32 + lane];
        float2 h2 = hb[(size_t)e1.x * 32 + lane];
        float2 h3 = hb[(size_t)e1.z * 32 + lane];
        fma2(accA, *(unsigned long long*)&h0, pack2(s0.x, s0.x));
        fma2(accB, *(unsigned long long*)&h1, pack2(s0.y, s0.y));
        fma2(accA, *(unsigned long long*)&h2, pack2(s1.x, s1.x));
        fma2(accB, *(unsigned long long*)&h3, pack2(s1.y, s1.y));
    }
    if (j + 2 <= end) {
        int4   e0 = *(const int4*)&g_edge[j];
        float2 s0 = *(const float2*)&g_escore[j];
        float2 h0 = hb[(size_t)e0.x * 32 + lane];
        float2 h1 = hb[(size_t)e0.z * 32 + lane];
        fma2(accA, *(unsigned long long*)&h0, pack2(s0.x, s0.x));
        fma2(accB, *(unsigned long long*)&h1, pack2(s0.y, s0.y));
        j += 2;
    }
    if (j < end) {
        int2 ed = g_edge[j];
        float e = g_escore[j];
        float2 hvv = hb[(size_t)ed.x * 32 + lane];
        fma2(accA, *(unsigned long long*)&hvv, pack2(e, e));
    }

    float inv = (end > beg) ? (1.0f / esum) : 0.0f;
    float2 hd = hb[(size_t)warp * 32 + lane];
    float2 aA = unpack2(accA), aB = unpack2(accB);
    float2 o;
    o.x = hd.x - (aA.x + aB.x) * inv;
    o.y = hd.y - (aA.y + aB.y) * inv;
    o.x = o.x > 0.f ? o.x : 0.f;
    o.y = o.y > 0.f ? o.y : 0.f;
    ((float2*)out)[(size_t)warp * 32 + lane] = o;
}

// ---------------------------------------------------------------------------
extern "C" void kernel_launch(void* const* d_in, const int* in_sizes, int n_in,
                              void* d_out, int out_size)
{
    const float* x   = (const float*)d_in[0];   // [N, 256]
    const float* W1  = (const float*)d_in[1];   // [64, 256]
    const float* W2  = (const float*)d_in[2];   // [64, 64]
    const float* a   = (const float*)d_in[3];   // [128, 1]
    const int*   src = (const int*)d_in[4];     // [E]
    const int*   dst = (const int*)d_in[5];     // [E]
    float* out = (float*)d_out;

    int N = in_sizes[0] / 256;
    int E = in_sizes[4];

    cudaFuncSetAttribute(fused_mlp_hist_kernel,
                         cudaFuncAttributeMaxDynamicSharedMemorySize,
                         SMEM_FLOATS * 4);

    int mlp_blocks = (N + 127) / 128;
    fused_mlp_hist_kernel<<<mlp_blocks + HIST_BLOCKS, 256, SMEM_FLOATS * 4>>>(
        x, W1, W2, a, dst, N, E, mlp_blocks);

    int sblocks = (N + SCAN_CHUNK - 1) / SCAN_CHUNK;
    scan_sum_kernel<<<sblocks, 256>>>(N);
    scan_mid_kernel<<<1, 128>>>(sblocks, E);
    scan_local_kernel<<<sblocks, 256>>>(N, E);

    scatter_kernel<<<(E + 255) / 256, 256>>>(src, dst, E);
    aggregate_kernel<<<(N * 32 + 255) / 256, 256>>>(out, N);
}